// round 2
// baseline (speedup 1.0000x reference)
#include <cuda_runtime.h>

typedef unsigned long long u64;

__device__ __forceinline__ u64 pk2(float a, float b) {
    u64 r; asm("mov.b64 %0,{%1,%2};" : "=l"(r) : "f"(a), "f"(b)); return r;
}
__device__ __forceinline__ void fma2(u64& d, u64 a, u64 b) {
    asm("fma.rn.f32x2 %0,%1,%2,%0;" : "+l"(d) : "l"(a), "l"(b));
}
__device__ __forceinline__ float rsum(u64 v) {
    float lo, hi; asm("mov.b64 {%0,%1},%2;" : "=f"(lo), "=f"(hi) : "l"(v));
    return lo + hi;
}
__device__ __forceinline__ float tanh_f(float x) {
    float e = __expf(2.f * x);
    return 1.f - __fdividef(2.f, e + 1.f);
}
__device__ __forceinline__ void cp16(float* dst, const float* src) {
    unsigned d = (unsigned)__cvta_generic_to_shared(dst);
    asm volatile("cp.async.cg.shared.global [%0],[%1],16;" :: "r"(d), "l"(src));
}
__device__ __forceinline__ void cp_commit() { asm volatile("cp.async.commit_group;"); }
template<int N> __device__ __forceinline__ void cp_wait() {
    asm volatile("cp.async.wait_group %0;" :: "n"(N));
}

struct Params {
    const float* Wh[5];
    const float* Bh[5];
    const float* W0; const float* B0;
    const float* W6; const float* B6;
    const float* bc[5];
    const float* f1;
    const float* inp;
    const float* realv;
};

// ============================ zero kernel ==================================
__global__ void zero_kernel(float* out) {
    if (threadIdx.x < 3) out[threadIdx.x] = 0.f;
}

// ======================= pipelined 256x256 layer ===========================
// 256 threads = 64 quads (4 consecutive neurons) x 4 rowgroups (RPG rows).
// Weights streamed gmem->smem via cp.async ring (4 x 8KB), acts broadcast LDS.
template<int RPG>
__device__ __forceinline__ void layer_mm(
    const float* __restrict__ Wl, const float* __restrict__ hin,
    float* __restrict__ wbuf, u64 (&acc)[RPG][4],
    int tid, int q, int rgbase)
{
    const float* wsrc = Wl + tid * 8;
    float* wdst = wbuf + tid * 8;
    #pragma unroll
    for (int cc = 0; cc < 3; cc++) {
        cp16(wdst + cc * 2048, wsrc + cc * 2048);
        cp16(wdst + cc * 2048 + 4, wsrc + cc * 2048 + 4);
        cp_commit();
    }
    #pragma unroll 1
    for (int c = 0; c < 32; c++) {
        cp_wait<2>();
        __syncthreads();
        if (c < 29) {
            float* db = wbuf + ((c + 3) & 3) * 2048 + tid * 8;
            const float* sb = Wl + (c + 3) * 2048 + tid * 8;
            cp16(db, sb); cp16(db + 4, sb + 4); cp_commit();
        }
        const float* ws = wbuf + (c & 3) * 2048 + 4 * q;
        u64 wp[4][4];
        #pragma unroll
        for (int kp = 0; kp < 4; kp++) {
            float4 w0 = *(const float4*)(ws + (2 * kp) * 256);
            float4 w1 = *(const float4*)(ws + (2 * kp + 1) * 256);
            wp[kp][0] = pk2(w0.x, w1.x); wp[kp][1] = pk2(w0.y, w1.y);
            wp[kp][2] = pk2(w0.z, w1.z); wp[kp][3] = pk2(w0.w, w1.w);
        }
        const float* hbase = hin + rgbase * 256 + c * 8;
        #pragma unroll
        for (int rr = 0; rr < RPG; rr++) {
            ulonglong2 va = *(const ulonglong2*)(hbase + rr * 256);
            ulonglong2 vb = *(const ulonglong2*)(hbase + rr * 256 + 4);
            #pragma unroll
            for (int n = 0; n < 4; n++) {
                fma2(acc[rr][n], va.x, wp[0][n]);
                fma2(acc[rr][n], va.y, wp[1][n]);
                fma2(acc[rr][n], vb.x, wp[2][n]);
                fma2(acc[rr][n], vb.y, wp[3][n]);
            }
        }
    }
}

// ============================ forward kernel ===============================
// 32 points / block; rowgroup rg owns points [rg*8, rg*8+8).
#define FWD_SMEM_FLOATS (8192*3 + 64 + 256 + 2)

__global__ __launch_bounds__(256) void fwd_kernel(Params P, float* __restrict__ out) {
    extern __shared__ float sm[];
    float* h0   = sm;
    float* h1   = sm + 8192;
    float* wbuf = sm + 16384;
    float* xs   = sm + 24576;     // 64
    float* redm = sm + 24640;     // 256
    float* bins = sm + 24896;     // 2

    const int tid = threadIdx.x;
    const int q = tid & 63, rg = tid >> 6;
    const int lane = tid & 31, w = tid >> 5;
    const int base = blockIdx.x * 32;

    if (tid < 32) {
        int g = base + tid;
        int gg = g < 36999 ? g : 36999;
        const float* src; int i;
        if      (gg <  1000) { src = P.bc[0]; i = gg; }
        else if (gg <  2000) { src = P.bc[1]; i = gg - 1000; }
        else if (gg <  7000) { src = P.bc[2]; i = gg - 2000; }
        else if (gg < 12000) { src = P.bc[3]; i = gg - 7000; }
        else if (gg < 17000) { src = P.bc[4]; i = gg - 12000; }
        else                 { src = P.inp;   i = gg - 17000; }
        float2 v = ((const float2*)src)[i];
        xs[2 * tid] = v.x; xs[2 * tid + 1] = v.y;
    }
    if (tid < 2) bins[tid] = 0.f;

    float4 w0a = *(const float4*)(P.W0 + 4 * q);
    float4 w0b = *(const float4*)(P.W0 + 256 + 4 * q);
    float4 b0  = *(const float4*)(P.B0 + 4 * q);
    float4 w6r[4];
    #pragma unroll
    for (int n = 0; n < 4; n++) w6r[n] = *(const float4*)(P.W6 + (4 * q + n) * 4);
    __syncthreads();

    #pragma unroll
    for (int rr = 0; rr < 8; rr++) {
        int p = rg * 8 + rr;
        float z = xs[2 * p], r = xs[2 * p + 1];
        float4 t;
        t.x = tanh_f(fmaf(r, w0b.x, fmaf(z, w0a.x, b0.x)));
        t.y = tanh_f(fmaf(r, w0b.y, fmaf(z, w0a.y, b0.y)));
        t.z = tanh_f(fmaf(r, w0b.z, fmaf(z, w0a.z, b0.z)));
        t.w = tanh_f(fmaf(r, w0b.w, fmaf(z, w0a.w, b0.w)));
        *(float4*)(h0 + p * 256 + 4 * q) = t;
    }

    float* hin = h0; float* hout = h1;
    float part[8][4];
    #pragma unroll
    for (int rr = 0; rr < 8; rr++)
        #pragma unroll
        for (int c = 0; c < 4; c++) part[rr][c] = 0.f;

    #pragma unroll 1
    for (int l = 0; l < 5; l++) {
        u64 acc[8][4];
        #pragma unroll
        for (int rr = 0; rr < 8; rr++)
            #pragma unroll
            for (int n = 0; n < 4; n++) acc[rr][n] = 0ull;

        layer_mm<8>(P.Wh[l], hin, wbuf, acc, tid, q, rg * 8);

        float4 bl = *(const float4*)(P.Bh[l] + 4 * q);
        float bb[4] = {bl.x, bl.y, bl.z, bl.w};
        if (l < 4) {
            #pragma unroll
            for (int rr = 0; rr < 8; rr++) {
                float4 t;
                t.x = tanh_f(rsum(acc[rr][0]) + bb[0]);
                t.y = tanh_f(rsum(acc[rr][1]) + bb[1]);
                t.z = tanh_f(rsum(acc[rr][2]) + bb[2]);
                t.w = tanh_f(rsum(acc[rr][3]) + bb[3]);
                *(float4*)(hout + (rg * 8 + rr) * 256 + 4 * q) = t;
            }
            float* tmp = hin; hin = hout; hout = tmp;
        } else {
            #pragma unroll
            for (int rr = 0; rr < 8; rr++) {
                #pragma unroll
                for (int n = 0; n < 4; n++) {
                    float t = tanh_f(rsum(acc[rr][n]) + bb[n]);
                    part[rr][0] = fmaf(t, w6r[n].x, part[rr][0]);
                    part[rr][1] = fmaf(t, w6r[n].y, part[rr][1]);
                    part[rr][2] = fmaf(t, w6r[n].z, part[rr][2]);
                    part[rr][3] = fmaf(t, w6r[n].w, part[rr][3]);
                }
            }
        }
    }

    // reduce partials across the 32 lanes of each warp
    #pragma unroll
    for (int rr = 0; rr < 8; rr++)
        #pragma unroll
        for (int c = 0; c < 4; c++) {
            float v = part[rr][c];
            v += __shfl_xor_sync(~0u, v, 16);
            v += __shfl_xor_sync(~0u, v, 8);
            v += __shfl_xor_sync(~0u, v, 4);
            v += __shfl_xor_sync(~0u, v, 2);
            v += __shfl_xor_sync(~0u, v, 1);
            part[rr][c] = v;
        }
    if (lane == 0) {
        #pragma unroll
        for (int rr = 0; rr < 8; rr++)
            *(float4*)(redm + w * 32 + rr * 4) =
                make_float4(part[rr][0], part[rr][1], part[rr][2], part[rr][3]);
    }
    __syncthreads();

    if (tid < 128) {
        int p = tid >> 2, c = tid & 3;
        int prg = p >> 3, rr = p & 7;
        float o = redm[(2 * prg) * 32 + rr * 4 + c]
                + redm[(2 * prg + 1) * 32 + rr * 4 + c] + P.B6[c];
        int g = base + p;
        if (g < 37000) {
            if (g < 17000) {
                float sc; bool use; float tgt = 0.f;
                if      (g <  2000) { sc = 0.001f;  use = (c < 3); }
                else if (g <  7000) { sc = 0.0002f; use = (c < 3); if (c == 1) tgt = 1.f; }
                else if (g < 12000) { sc = 0.0002f; use = (c < 3); }
                else                { sc = 0.0002f; use = (c == 3); }
                if (use) { float d = o - tgt; atomicAdd(&bins[0], d * d * sc); }
            } else {
                float d = o - P.realv[(g - 17000) * 4 + c];
                atomicAdd(&bins[1], d * d * (1.f / 80000.f));
            }
        }
    }
    __syncthreads();
    if (tid == 0) { atomicAdd(&out[0], bins[0]); atomicAdd(&out[1], bins[1]); }
}

// ============================ PDE kernel ===================================
// 8 points / block, 5 Taylor streams. Row r = p*5 + s (point-major so the
// tanh chain rule stays thread-local). rg owns rows [rg*10, rg*10+10)
// = points {2rg, 2rg+1} x 5 streams.
#define PDE_SMEM_FLOATS (10240*2 + 8192 + 16 + 160 + 320 + 4)

__global__ __launch_bounds__(256) void pde_kernel(Params P, float* __restrict__ out) {
    extern __shared__ float sm[];
    float* h0   = sm;
    float* h1   = sm + 10240;
    float* wbuf = sm + 20480;
    float* xs   = sm + 28672;    // 16
    float* outv = sm + 28688;    // 160
    float* redm = sm + 28848;    // 320
    float* bin  = sm + 29168;    // 1

    const int tid = threadIdx.x;
    const int q = tid & 63, rg = tid >> 6;
    const int lane = tid & 31, w = tid >> 5;
    const int base = blockIdx.x * 8;

    if (tid < 8) {
        float2 v = ((const float2*)P.f1)[base + tid];
        xs[2 * tid] = v.x; xs[2 * tid + 1] = v.y;
    }
    if (tid == 0) bin[0] = 0.f;

    float4 w0zv = *(const float4*)(P.W0 + 4 * q);
    float4 w0rv = *(const float4*)(P.W0 + 256 + 4 * q);
    float4 b0v  = *(const float4*)(P.B0 + 4 * q);
    float w0z[4] = {w0zv.x, w0zv.y, w0zv.z, w0zv.w};
    float w0r[4] = {w0rv.x, w0rv.y, w0rv.z, w0rv.w};
    float b0a[4] = {b0v.x, b0v.y, b0v.z, b0v.w};
    float4 w6r[4];
    #pragma unroll
    for (int n = 0; n < 4; n++) w6r[n] = *(const float4*)(P.W6 + (4 * q + n) * 4);
    __syncthreads();

    // layer 0: h=tanh(a), hz=g*w0z, hr=g*w0r, hzz=gg*w0z^2, hrr=gg*w0r^2
    #pragma unroll
    for (int pp = 0; pp < 2; pp++) {
        int p = rg * 2 + pp;
        float z = xs[2 * p], r = xs[2 * p + 1];
        float vo[5][4];
        #pragma unroll
        for (int n = 0; n < 4; n++) {
            float a = fmaf(r, w0r[n], fmaf(z, w0z[n], b0a[n]));
            float t = tanh_f(a);
            float g = 1.f - t * t;
            float gg = -2.f * t * g;
            vo[0][n] = t;
            vo[1][n] = g * w0z[n];
            vo[2][n] = g * w0r[n];
            vo[3][n] = gg * w0z[n] * w0z[n];
            vo[4][n] = gg * w0r[n] * w0r[n];
        }
        #pragma unroll
        for (int s = 0; s < 5; s++)
            *(float4*)(h0 + (p * 5 + s) * 256 + 4 * q) =
                make_float4(vo[s][0], vo[s][1], vo[s][2], vo[s][3]);
    }

    float* hin = h0; float* hout = h1;
    float part[10][4];
    #pragma unroll
    for (int rr = 0; rr < 10; rr++)
        #pragma unroll
        for (int c = 0; c < 4; c++) part[rr][c] = 0.f;

    #pragma unroll 1
    for (int l = 0; l < 5; l++) {
        u64 acc[10][4];
        #pragma unroll
        for (int rr = 0; rr < 10; rr++)
            #pragma unroll
            for (int n = 0; n < 4; n++) acc[rr][n] = 0ull;

        layer_mm<10>(P.Wh[l], hin, wbuf, acc, tid, q, rg * 10);

        float4 bl = *(const float4*)(P.Bh[l] + 4 * q);
        float bb[4] = {bl.x, bl.y, bl.z, bl.w};
        #pragma unroll
        for (int pp = 0; pp < 2; pp++) {
            int rb = pp * 5;
            float vo[5][4];
            #pragma unroll
            for (int n = 0; n < 4; n++) {
                float a   = rsum(acc[rb + 0][n]) + bb[n];
                float az  = rsum(acc[rb + 1][n]);
                float ar  = rsum(acc[rb + 2][n]);
                float azz = rsum(acc[rb + 3][n]);
                float arr = rsum(acc[rb + 4][n]);
                float t = tanh_f(a);
                float g = 1.f - t * t;
                float gg = -2.f * t * g;
                vo[0][n] = t;
                vo[1][n] = g * az;
                vo[2][n] = g * ar;
                vo[3][n] = fmaf(gg * az, az, g * azz);
                vo[4][n] = fmaf(gg * ar, ar, g * arr);
            }
            if (l < 4) {
                int p = rg * 2 + pp;
                #pragma unroll
                for (int s = 0; s < 5; s++)
                    *(float4*)(hout + (p * 5 + s) * 256 + 4 * q) =
                        make_float4(vo[s][0], vo[s][1], vo[s][2], vo[s][3]);
            } else {
                #pragma unroll
                for (int s = 0; s < 5; s++)
                    #pragma unroll
                    for (int n = 0; n < 4; n++) {
                        float t = vo[s][n];
                        part[rb + s][0] = fmaf(t, w6r[n].x, part[rb + s][0]);
                        part[rb + s][1] = fmaf(t, w6r[n].y, part[rb + s][1]);
                        part[rb + s][2] = fmaf(t, w6r[n].z, part[rb + s][2]);
                        part[rb + s][3] = fmaf(t, w6r[n].w, part[rb + s][3]);
                    }
            }
        }
        if (l < 4) { float* tmp = hin; hin = hout; hout = tmp; }
    }

    #pragma unroll
    for (int rr = 0; rr < 10; rr++)
        #pragma unroll
        for (int c = 0; c < 4; c++) {
            float v = part[rr][c];
            v += __shfl_xor_sync(~0u, v, 16);
            v += __shfl_xor_sync(~0u, v, 8);
            v += __shfl_xor_sync(~0u, v, 4);
            v += __shfl_xor_sync(~0u, v, 2);
            v += __shfl_xor_sync(~0u, v, 1);
            part[rr][c] = v;
        }
    if (lane == 0) {
        #pragma unroll
        for (int rr = 0; rr < 10; rr++)
            *(float4*)(redm + w * 40 + rr * 4) =
                make_float4(part[rr][0], part[rr][1], part[rr][2], part[rr][3]);
    }
    __syncthreads();

    if (tid < 160) {
        int p = tid / 20, rem = tid % 20;
        int s = rem >> 2, c = rem & 3;
        int prg = p >> 1, pp = p & 1;
        int rr = pp * 5 + s;
        float o = redm[(2 * prg) * 40 + rr * 4 + c]
                + redm[(2 * prg + 1) * 40 + rr * 4 + c];
        if (s == 0) o += P.B6[c];
        outv[p * 20 + s * 4 + c] = o;
    }
    __syncthreads();

    if (tid < 8) {
        int p = tid;
        float r = xs[2 * p + 1];
        const float* ov = outv + p * 20;
        float uz = ov[0],  us = ov[1],  ur = ov[2];
        float uz_z = ov[4], us_z = ov[5], ur_z = ov[6], p_z = ov[7];
        float uz_r = ov[8], us_r = ov[9], ur_r = ov[10], p_r = ov[11];
        float uz_zz = ov[12], us_zz = ov[13], ur_zz = ov[14];
        float uz_rr = ov[16], us_rr = ov[17], ur_rr = ov[18];
        const float NUc = 8e-4f;
        float inr = 1.f / r;
        float e1 = ur*ur_r + uz*ur_z - us*us*inr + p_r
                 - NUc*inr*ur_r - NUc*ur_rr - NUc*ur_zz + NUc*ur*inr*inr;
        float e2 = ur*us_r + uz*us_z + ur*us*inr
                 - NUc*inr*us_r - NUc*us_rr - NUc*us_zz + NUc*us*inr*inr;
        float e3 = ur*uz_r + uz*uz_z + p_z
                 - NUc*inr*uz_r - NUc*uz_rr - NUc*uz_zz;
        float e4 = ur + r*ur_r + r*uz_z;
        float v = (e1*e1 + e2*e2 + e3*e3 + e4*e4) * (1.f / 80000.f);
        atomicAdd(bin, v);
    }
    __syncthreads();
    if (tid == 0) atomicAdd(&out[2], bin[0]);
}

// ============================ launcher =====================================
extern "C" void kernel_launch(void* const* d_in, const int* in_sizes, int n_in,
                              void* d_out, int out_size) {
    const float* const* din = (const float* const*)d_in;
    Params P;
    P.W0 = din[0];  P.B0 = din[1];
    P.Wh[0] = din[2];  P.Bh[0] = din[3];
    P.Wh[1] = din[4];  P.Bh[1] = din[5];
    P.Wh[2] = din[6];  P.Bh[2] = din[7];
    P.Wh[3] = din[8];  P.Bh[3] = din[9];
    P.Wh[4] = din[10]; P.Bh[4] = din[11];
    P.W6 = din[12]; P.B6 = din[13];
    P.bc[0] = din[14]; P.bc[1] = din[15]; P.bc[2] = din[16];
    P.bc[3] = din[17]; P.bc[4] = din[18];
    P.f1 = din[19]; P.inp = din[20]; P.realv = din[21];

    float* out = (float*)d_out;

    const int fwd_smem = FWD_SMEM_FLOATS * 4;
    const int pde_smem = PDE_SMEM_FLOATS * 4;
    cudaFuncSetAttribute(fwd_kernel, cudaFuncAttributeMaxDynamicSharedMemorySize, fwd_smem);
    cudaFuncSetAttribute(pde_kernel, cudaFuncAttributeMaxDynamicSharedMemorySize, pde_smem);

    zero_kernel<<<1, 32>>>(out);
    fwd_kernel<<<(37000 + 31) / 32, 256, fwd_smem>>>(P, out);
    pde_kernel<<<20000 / 8, 256, pde_smem>>>(P, out);
}